// round 13
// baseline (speedup 1.0000x reference)
#include <cuda_runtime.h>
#include <cuda_bf16.h>
#include <mma.h>

using namespace nvcuda;

#define B_ 256
#define L_ 1026
#define D_ 1280
#define E_ 300
#define H_ 256
#define C_ 1580   // D_+E_

// SMEM layouts for the wmma GEMM (BK=32)
#define A_LD 36   // As[64][36]  (m-major, padded)
#define B_LD 68   // Bs[32][68]  (k-major, padded)
// As: 2304 floats; Bs: 2176; total 4480.  Epilogue: 4 warps * 1024 = 4096.

// ---- scratch (device globals; no allocation allowed) ----
__device__ float g_pooled[B_ * D_];
__device__ float g_inv[B_];
__device__ float g_x1[B_ * D_];      // PRE-relu x1 (consumers apply relu)
__device__ float g_q[B_ * E_];
__device__ float g_attn[B_ * B_];
__device__ float g_f1[B_ * E_];
__device__ float g_f2[B_ * D_];
__device__ float g_comb[B_ * C_];
__device__ float g_h[B_ * H_];

// ------------------------------------------------------------------
// init accumulators + inv counts
// ------------------------------------------------------------------
__global__ void init_all_kernel(const int* __restrict__ lens,
                                const float* __restrict__ b_prot,
                                const float* __restrict__ b_attn) {
    int i = blockIdx.x * blockDim.x + threadIdx.x;
    if (i < B_ * D_) {
        g_pooled[i] = 0.f;
        g_f2[i] = 0.f;
        g_x1[i] = b_prot[i % D_];
    }
    if (i < B_ * E_) {
        g_f1[i] = 0.f;
        g_q[i] = b_attn[i % E_];
    }
    if (i < B_ * B_) g_attn[i] = 0.f;
    if (i < B_ * H_) g_h[i] = 0.f;
    if (i < B_) {
        int len = lens[i];
        g_inv[i] = 1.f / fmaxf((float)(len - 2), 1.f);
    }
}

// ------------------------------------------------------------------
// ragged masked sum pooling (chunked, load-balanced)
// ------------------------------------------------------------------
#define TL 128
__global__ void pool_kernel(const float* __restrict__ tok,
                            const int* __restrict__ lens) {
    int b = blockIdx.x;
    int len = lens[b];
    int l0 = blockIdx.y * TL;
    if (l0 < 1) l0 = 1;
    int l1 = min((int)(blockIdx.y + 1) * TL, len - 1);
    if (l0 >= l1) return;

    int d4 = threadIdx.x;  // 0..319
    const float4* base = reinterpret_cast<const float4*>(tok)
                       + (size_t)b * L_ * (D_ / 4) + d4;
    float4 acc = make_float4(0.f, 0.f, 0.f, 0.f);
    for (int l = l0; l < l1; l++) {
        float4 v = base[(size_t)l * (D_ / 4)];
        acc.x += v.x; acc.y += v.y; acc.z += v.z; acc.w += v.w;
    }
    float* o = g_pooled + b * D_ + d4 * 4;
    atomicAdd(o + 0, acc.x);
    atomicAdd(o + 1, acc.y);
    atomicAdd(o + 2, acc.z);
    atomicAdd(o + 3, acc.w);
}

// ------------------------------------------------------------------
// relu + tf32-truncate a float4 (conversion hoisted into staging)
// ------------------------------------------------------------------
template <int RELU>
__device__ __forceinline__ float4 prep4(float4 v) {
    if (RELU) {
        v.x = fmaxf(v.x, 0.f); v.y = fmaxf(v.y, 0.f);
        v.z = fmaxf(v.z, 0.f); v.w = fmaxf(v.w, 0.f);
    }
    v.x = wmma::__float_to_tf32(v.x);
    v.y = wmma::__float_to_tf32(v.y);
    v.z = wmma::__float_to_tf32(v.z);
    v.w = wmma::__float_to_tf32(v.w);
    return v;
}

// ------------------------------------------------------------------
// split-K tf32 wmma GEMM body, BK=32, 128 threads (4 warps, 2x2),
// warp tile 32x32 (4 accumulator fragments).
//   C[M,N] += sum_{k in split} sc[m] * A_eff(m,k)*B_eff(k,n)
// ------------------------------------------------------------------
template <int TA, int TB, int RELUA, int RELUB, int SCALEA>
__device__ __forceinline__ void gemm_body(float* smem,
                                          const float* __restrict__ A,
                                          const float* __restrict__ B,
                                          const float* __restrict__ rscale,
                                          float* __restrict__ C,
                                          int M, int N, int K, int lda, int ldb,
                                          int tiles_per_split, int zi) {
    float* As = smem;              // [64][A_LD]
    float* Bs = smem + 2304;       // [32][B_LD]

    int k_begin = zi * tiles_per_split * 32;
    if (k_begin >= K) return;
    int k_end = min(k_begin + tiles_per_split * 32, K);

    int t = threadIdx.x;           // 0..127
    int bm = blockIdx.y * 64;
    int bn = blockIdx.x * 64;
    int wid = t >> 5;              // 0..3
    int warp_m = wid & 1;          // 32-row half
    int warp_n = wid >> 1;         // 32-col half

    wmma::fragment<wmma::accumulator, 16, 16, 8, float> cf[2][2];
#pragma unroll
    for (int i = 0; i < 2; i++)
#pragma unroll
        for (int j = 0; j < 2; j++) wmma::fill_fragment(cf[i][j], 0.f);

    for (int k0 = k_begin; k0 < k_end; k0 += 32) {
        // ---- stage A tile -> As[m][k], tf32-converted ----
        if (!TA) {
            int mm = t >> 1;             // 0..63
            int kk16 = (t & 1) * 16;
#pragma unroll
            for (int h = 0; h < 4; h++) {
                int kk4 = kk16 + h * 4;
                float4 v = make_float4(0.f, 0.f, 0.f, 0.f);
                if (k0 + kk4 < K)
                    v = *reinterpret_cast<const float4*>(
                            &A[(size_t)(bm + mm) * lda + k0 + kk4]);
                v = prep4<RELUA>(v);
                *reinterpret_cast<float4*>(&As[mm * A_LD + kk4]) = v;
            }
        } else {
            int kk = t >> 2;             // 0..31
            int mm16 = (t & 3) * 16;
#pragma unroll
            for (int h = 0; h < 4; h++) {
                int mm4 = mm16 + h * 4;
                float4 v = make_float4(0.f, 0.f, 0.f, 0.f);
                if (k0 + kk < K)
                    v = *reinterpret_cast<const float4*>(
                            &A[(size_t)(k0 + kk) * lda + bm + mm4]);
                v = prep4<RELUA>(v);
                As[(mm4 + 0) * A_LD + kk] = v.x;
                As[(mm4 + 1) * A_LD + kk] = v.y;
                As[(mm4 + 2) * A_LD + kk] = v.z;
                As[(mm4 + 3) * A_LD + kk] = v.w;
            }
        }
        // ---- stage B tile -> Bs[k][n], tf32-converted ----
        if (!TB) {
            int kk = t >> 2;             // 0..31
            int nn16 = (t & 3) * 16;
#pragma unroll
            for (int h = 0; h < 4; h++) {
                int nn4 = nn16 + h * 4;
                float4 v = make_float4(0.f, 0.f, 0.f, 0.f);
                if (k0 + kk < K && bn + nn4 < N)
                    v = *reinterpret_cast<const float4*>(
                            &B[(size_t)(k0 + kk) * ldb + bn + nn4]);
                v = prep4<RELUB>(v);
                *reinterpret_cast<float4*>(&Bs[kk * B_LD + nn4]) = v;
            }
        } else {
            int nn = t >> 1;             // 0..63
            int kk16 = (t & 1) * 16;
#pragma unroll
            for (int h = 0; h < 4; h++) {
                int kk4 = kk16 + h * 4;
                float4 v = make_float4(0.f, 0.f, 0.f, 0.f);
                if (bn + nn < N && k0 + kk4 < K)
                    v = *reinterpret_cast<const float4*>(
                            &B[(size_t)(bn + nn) * ldb + k0 + kk4]);
                v = prep4<RELUB>(v);
                Bs[(kk4 + 0) * B_LD + nn] = v.x;
                Bs[(kk4 + 1) * B_LD + nn] = v.y;
                Bs[(kk4 + 2) * B_LD + nn] = v.z;
                Bs[(kk4 + 3) * B_LD + nn] = v.w;
            }
        }
        __syncthreads();

#pragma unroll
        for (int kk = 0; kk < 32; kk += 8) {
            wmma::fragment<wmma::matrix_b, 16, 16, 8,
                           wmma::precision::tf32, wmma::row_major> bf[2];
#pragma unroll
            for (int j = 0; j < 2; j++)
                wmma::load_matrix_sync(
                    bf[j], &Bs[kk * B_LD + warp_n * 32 + j * 16], B_LD);
#pragma unroll
            for (int ma = 0; ma < 2; ma++) {
                wmma::fragment<wmma::matrix_a, 16, 16, 8,
                               wmma::precision::tf32, wmma::row_major> af;
                wmma::load_matrix_sync(
                    af, &As[(warp_m * 32 + ma * 16) * A_LD + kk], A_LD);
#pragma unroll
                for (int j = 0; j < 2; j++)
                    wmma::mma_sync(cf[ma][j], af, bf[j], cf[ma][j]);
            }
        }
        __syncthreads();
    }

    // ---- epilogue: stage fragments to SMEM, then atomicAdd to C ----
    float* epi = smem + wid * 1024;  // 4 fragments x 256 per warp
#pragma unroll
    for (int ma = 0; ma < 2; ma++)
#pragma unroll
        for (int j = 0; j < 2; j++)
            wmma::store_matrix_sync(epi + (ma * 2 + j) * 256, cf[ma][j],
                                    16, wmma::mem_row_major);
    __syncwarp();

    int lane = t & 31;
    for (int idx = lane; idx < 1024; idx += 32) {
        int ma = idx >> 9;
        int j = (idx >> 8) & 1;
        int r = (idx & 255) >> 4;
        int c = idx & 15;
        int gm = bm + warp_m * 32 + ma * 16 + r;
        int gn = bn + warp_n * 32 + j * 16 + c;
        if (gn < N) {
            float v = epi[idx];
            if (SCALEA) v *= rscale[gm];
            atomicAdd(&C[(size_t)gm * N + gn], v);
        }
    }
}

template <int TA, int TB, int RELUA, int RELUB, int SCALEA>
__global__ void gemm_kernel(const float* __restrict__ A,
                            const float* __restrict__ B,
                            const float* __restrict__ rscale,
                            float* __restrict__ C,
                            int M, int N, int K, int lda, int ldb,
                            int tiles_per_split) {
    __shared__ float smem[4480];
    gemm_body<TA, TB, RELUA, RELUB, SCALEA>(smem, A, B, rscale, C,
                                            M, N, K, lda, ldb,
                                            tiles_per_split, blockIdx.z);
}

// ------------------------------------------------------------------
// fused steps 6+7: blockIdx.z < z1 -> f1 = attn @ x2 ;
//                  else            -> f2 = attn^T @ relu(x1)
// ------------------------------------------------------------------
__global__ void gemm67_kernel(const float* __restrict__ attn,
                              const float* __restrict__ x2,
                              int z1, int tps1, int tps2) {
    __shared__ float smem[4480];
    if ((int)blockIdx.z < z1) {
        if (blockIdx.x >= (E_ + 63) / 64) return;
        gemm_body<0, 0, 0, 0, 0>(smem, attn, x2, nullptr, g_f1,
                                 B_, E_, B_, B_, E_, tps1, blockIdx.z);
    } else {
        gemm_body<1, 0, 0, 1, 0>(smem, attn, g_x1, nullptr, g_f2,
                                 B_, D_, B_, B_, D_, tps2, blockIdx.z - z1);
    }
}

// ------------------------------------------------------------------
// row softmax in-place: one block (256 threads) per row
// ------------------------------------------------------------------
__global__ void row_softmax_kernel(float* __restrict__ X, int N) {
    int r = blockIdx.x;
    float* x = X + (size_t)r * N;
    int t = threadIdx.x;
    __shared__ float red[8];

    float m = -1e30f;
    for (int i = t; i < N; i += 256) m = fmaxf(m, x[i]);
#pragma unroll
    for (int o = 16; o > 0; o >>= 1) m = fmaxf(m, __shfl_xor_sync(0xffffffffu, m, o));
    if ((t & 31) == 0) red[t >> 5] = m;
    __syncthreads();
    if (t < 8) {
        float v = red[t];
#pragma unroll
        for (int o = 4; o > 0; o >>= 1) v = fmaxf(v, __shfl_xor_sync(0xffu, v, o));
        if (t == 0) red[0] = v;
    }
    __syncthreads();
    m = red[0];
    __syncthreads();

    float s = 0.f;
    for (int i = t; i < N; i += 256) {
        float e = __expf(x[i] - m);
        x[i] = e;
        s += e;
    }
#pragma unroll
    for (int o = 16; o > 0; o >>= 1) s += __shfl_xor_sync(0xffffffffu, s, o);
    if ((t & 31) == 0) red[t >> 5] = s;
    __syncthreads();
    if (t < 8) {
        float v = red[t];
#pragma unroll
        for (int o = 4; o > 0; o >>= 1) v += __shfl_xor_sync(0xffu, v, o);
        if (t == 0) red[0] = v;
    }
    __syncthreads();
    float inv = 1.f / red[0];
    for (int i = t; i < N; i += 256) x[i] *= inv;
}

// ------------------------------------------------------------------
// fused dual softmax+combine (512 blocks)
// ------------------------------------------------------------------
__global__ void softmax_combine2_kernel(const float* __restrict__ x2) {
    int rb = blockIdx.x;
    float* x;
    const float* bs;
    float* cb;
    int N, relu_base;
    if (rb < B_) {
        int r = rb;
        x = g_f1 + (size_t)r * E_;
        bs = x2 + (size_t)r * E_;
        cb = g_comb + (size_t)r * C_ + D_;
        N = E_; relu_base = 0;
    } else {
        int r = rb - B_;
        x = g_f2 + (size_t)r * D_;
        bs = g_x1 + (size_t)r * D_;
        cb = g_comb + (size_t)r * C_;
        N = D_; relu_base = 1;
    }
    int t = threadIdx.x;
    __shared__ float red[8];

    float m = -1e30f;
    for (int i = t; i < N; i += 256) m = fmaxf(m, x[i]);
#pragma unroll
    for (int o = 16; o > 0; o >>= 1) m = fmaxf(m, __shfl_xor_sync(0xffffffffu, m, o));
    if ((t & 31) == 0) red[t >> 5] = m;
    __syncthreads();
    if (t < 8) {
        float v = red[t];
#pragma unroll
        for (int o = 4; o > 0; o >>= 1) v = fmaxf(v, __shfl_xor_sync(0xffu, v, o));
        if (t == 0) red[0] = v;
    }
    __syncthreads();
    m = red[0];
    __syncthreads();

    float s = 0.f;
    for (int i = t; i < N; i += 256) {
        float e = __expf(x[i] - m);
        x[i] = e;
        s += e;
    }
#pragma unroll
    for (int o = 16; o > 0; o >>= 1) s += __shfl_xor_sync(0xffffffffu, s, o);
    if ((t & 31) == 0) red[t >> 5] = s;
    __syncthreads();
    if (t < 8) {
        float v = red[t];
#pragma unroll
        for (int o = 4; o > 0; o >>= 1) v += __shfl_xor_sync(0xffu, v, o);
        if (t == 0) red[0] = v;
    }
    __syncthreads();
    float inv = 1.f / red[0];
    for (int i = t; i < N; i += 256) {
        float b = bs[i];
        if (relu_base) b = fmaxf(b, 0.f);
        cb[i] = b * (x[i] * inv + 1.f);
    }
}

// ------------------------------------------------------------------
// out[b] = sum_h relu(g_h[b,h] + b_fc1[h]) * W2[h] + b2[0]
// ------------------------------------------------------------------
__global__ void final_kernel(const float* __restrict__ b1,
                             const float* __restrict__ W2,
                             const float* __restrict__ b2,
                             float* __restrict__ out) {
    int b = blockIdx.x;
    int t = threadIdx.x;
    __shared__ float red[8];
    float v = fmaxf(g_h[b * H_ + t] + b1[t], 0.f) * W2[t];
#pragma unroll
    for (int o = 16; o > 0; o >>= 1) v += __shfl_xor_sync(0xffffffffu, v, o);
    if ((t & 31) == 0) red[t >> 5] = v;
    __syncthreads();
    if (t < 8) {
        float s = red[t];
#pragma unroll
        for (int o = 4; o > 0; o >>= 1) s += __shfl_xor_sync(0xffu, s, o);
        if (t == 0) out[b] = s + b2[0];
    }
}

// ------------------------------------------------------------------
static inline int ceil_div(int a, int b) { return (a + b - 1) / b; }

extern "C" void kernel_launch(void* const* d_in, const int* in_sizes, int n_in,
                              void* d_out, int out_size) {
    const float* token_reps = (const float*)d_in[0];
    const int*   batch_lens = (const int*)d_in[1];
    const float* mol_repr   = (const float*)d_in[2];
    const float* W_prot     = (const float*)d_in[3];
    const float* b_prot     = (const float*)d_in[4];
    const float* W_attn     = (const float*)d_in[5];
    const float* b_attn     = (const float*)d_in[6];
    const float* W_fc1      = (const float*)d_in[7];
    const float* b_fc1      = (const float*)d_in[8];
    const float* W_fc2      = (const float*)d_in[9];
    const float* b_fc2      = (const float*)d_in[10];
    float* out = (float*)d_out;

    float *p_pooled, *p_inv, *p_x1, *p_q, *p_attn, *p_comb, *p_h;
    cudaGetSymbolAddress((void**)&p_pooled, g_pooled);
    cudaGetSymbolAddress((void**)&p_inv,    g_inv);
    cudaGetSymbolAddress((void**)&p_x1,     g_x1);
    cudaGetSymbolAddress((void**)&p_q,      g_q);
    cudaGetSymbolAddress((void**)&p_attn,   g_attn);
    cudaGetSymbolAddress((void**)&p_comb,   g_comb);
    cudaGetSymbolAddress((void**)&p_h,      g_h);

    // 1) init accumulators (biases folded in) + inverse counts
    init_all_kernel<<<ceil_div(B_ * D_, 256), 256>>>(batch_lens, b_prot, b_attn);

    // 2) ragged masked sum pool (chunked, load-balanced)
    pool_kernel<<<dim3(B_, ceil_div(L_, TL)), D_ / 4>>>(token_reps, batch_lens);

    // 3) x1(pre-relu) = (pooled*inv) @ W_prot  [256,1280], K=1280 (40 k-tiles)
    {
        int tps = 5;   // -> 8 splits
        dim3 grid(D_ / 64, B_ / 64, 8);   // 640 blocks
        gemm_kernel<0, 0, 0, 0, 1><<<grid, 128>>>(
            p_pooled, W_prot, p_inv, p_x1, B_, D_, D_, D_, D_, tps);
    }

    // 4) q = relu(x1) @ W_attn  [256,300], K=1280 (40 k-tiles)
    {
        int tps = 3;   // -> 14 splits
        dim3 grid(ceil_div(E_, 64), B_ / 64, 14);  // 280 blocks
        gemm_kernel<0, 0, 1, 0, 0><<<grid, 128>>>(
            p_x1, W_attn, nullptr, p_q, B_, E_, D_, D_, E_, tps);
    }

    // 5) attn = softmax(q @ x2^T)  [256,256], K=300 (10 k-tiles)
    {
        int tps = 1;   // -> 10 splits
        dim3 grid(B_ / 64, B_ / 64, 10);  // 160 blocks
        gemm_kernel<0, 1, 0, 0, 0><<<grid, 128>>>(
            p_q, mol_repr, nullptr, p_attn, B_, B_, E_, E_, E_, tps);
        row_softmax_kernel<<<B_, 256>>>(p_attn, B_);
    }

    // 6+7) f1 = attn @ x2 ; f2 = attn^T @ relu(x1)  (one launch, z-split)
    {
        int z1 = 8, tps1 = 1;   // f1: K=256 -> 8 tiles -> 8 splits
        int z2 = 4, tps2 = 2;   // f2: 8 tiles -> 4 splits
        dim3 grid(D_ / 64, B_ / 64, z1 + z2);  // 20x4x12
        gemm67_kernel<<<grid, 128>>>(p_attn, mol_repr, z1, tps1, tps2);
    }

    // softmax+combine both halves (one launch, 512 blocks)
    softmax_combine2_kernel<<<2 * B_, 256>>>(mol_repr);

    // 8) h = combined @ W_fc1  [256,256], K=1580 (50 k-tiles)
    {
        int tps = 2;   // -> 25 splits
        dim3 grid(H_ / 64, B_ / 64, 25);  // 400 blocks
        gemm_kernel<0, 0, 0, 0, 0><<<grid, 128>>>(
            p_comb, W_fc1, nullptr, p_h, B_, H_, C_, C_, H_, tps);
    }

    // 9) out = relu(h + b_fc1) @ W_fc2 + b_fc2  [256,1]
    final_kernel<<<B_, 256>>>(b_fc1, W_fc2, b_fc2, out);
}